// round 3
// baseline (speedup 1.0000x reference)
#include <cuda_runtime.h>
#include <math.h>

#define BB 8
#define NN 2048
#define DD 512

// Scratch (allocation-free rule: __device__ globals). 96 MB total.
__device__ float g_Q [BB * NN * DD];            // raw q (sigmoid applied in final epilogue)
__device__ float g_KV[BB * NN * DD];            // exp(k) * v
__device__ float g_KW[BB * NN * DD];            // exp(k)

// ---------------------------------------------------------------------------
// Kernel A: fused QKV projection.  y = x @ W^T for Wq, Wk, Wv sharing X tiles.
// Tile: 64(M) x 64(N) x 16(K). 256 threads, 4x4 microtile per thread per matrix.
// Epilogue writes Q raw, KW = exp(K), KV = exp(K)*V.
// ---------------------------------------------------------------------------
__global__ __launch_bounds__(256) void qkv_kernel(
    const float* __restrict__ x,
    const float* __restrict__ Wq,
    const float* __restrict__ Wk,
    const float* __restrict__ Wv)
{
    __shared__ float Xs[16][68];   // [k][m], pad 4 keeps float4 alignment + no conflicts
    __shared__ float Qs[16][68];   // [k][n]
    __shared__ float Ks[16][68];
    __shared__ float Vs[16][68];

    const int tid = threadIdx.x;
    const int tx  = tid & 15;        // 0..15  (output col group)
    const int ty  = tid >> 4;        // 0..15  (output row group)
    const int row0 = blockIdx.y * 64;
    const int col0 = blockIdx.x * 64;
    const int lr = tid >> 2;         // 0..63  loader row
    const int lc = (tid & 3) * 4;    // 0,4,8,12 loader col (float4)

    float accq[4][4] = {}, acck[4][4] = {}, accv[4][4] = {};

    for (int c0 = 0; c0 < DD; c0 += 16) {
        float4 xv = *(const float4*)&x [(size_t)(row0 + lr) * DD + c0 + lc];
        float4 wq = *(const float4*)&Wq[(size_t)(col0 + lr) * DD + c0 + lc];
        float4 wk = *(const float4*)&Wk[(size_t)(col0 + lr) * DD + c0 + lc];
        float4 wv = *(const float4*)&Wv[(size_t)(col0 + lr) * DD + c0 + lc];
        Xs[lc + 0][lr] = xv.x; Xs[lc + 1][lr] = xv.y; Xs[lc + 2][lr] = xv.z; Xs[lc + 3][lr] = xv.w;
        Qs[lc + 0][lr] = wq.x; Qs[lc + 1][lr] = wq.y; Qs[lc + 2][lr] = wq.z; Qs[lc + 3][lr] = wq.w;
        Ks[lc + 0][lr] = wk.x; Ks[lc + 1][lr] = wk.y; Ks[lc + 2][lr] = wk.z; Ks[lc + 3][lr] = wk.w;
        Vs[lc + 0][lr] = wv.x; Vs[lc + 1][lr] = wv.y; Vs[lc + 2][lr] = wv.z; Vs[lc + 3][lr] = wv.w;
        __syncthreads();

        #pragma unroll
        for (int kk = 0; kk < 16; kk++) {
            float4 xr = *(const float4*)&Xs[kk][ty * 4];
            float4 qc = *(const float4*)&Qs[kk][tx * 4];
            float4 kc = *(const float4*)&Ks[kk][tx * 4];
            float4 vc = *(const float4*)&Vs[kk][tx * 4];
            float xa[4] = {xr.x, xr.y, xr.z, xr.w};
            float qa[4] = {qc.x, qc.y, qc.z, qc.w};
            float ka[4] = {kc.x, kc.y, kc.z, kc.w};
            float va[4] = {vc.x, vc.y, vc.z, vc.w};
            #pragma unroll
            for (int r = 0; r < 4; r++) {
                #pragma unroll
                for (int c = 0; c < 4; c++) {
                    accq[r][c] += xa[r] * qa[c];
                    acck[r][c] += xa[r] * ka[c];
                    accv[r][c] += xa[r] * va[c];
                }
            }
        }
        __syncthreads();
    }

    #pragma unroll
    for (int r = 0; r < 4; r++) {
        const int n = row0 + ty * 4 + r;
        const size_t base = (size_t)n * DD + col0 + tx * 4;
        float ew0 = expf(acck[r][0]);
        float ew1 = expf(acck[r][1]);
        float ew2 = expf(acck[r][2]);
        float ew3 = expf(acck[r][3]);
        *(float4*)&g_Q [base] = make_float4(accq[r][0], accq[r][1], accq[r][2], accq[r][3]);
        *(float4*)&g_KW[base] = make_float4(ew0, ew1, ew2, ew3);
        *(float4*)&g_KV[base] = make_float4(ew0 * accv[r][0], ew1 * accv[r][1],
                                            ew2 * accv[r][2], ew3 * accv[r][3]);
    }
}

// ---------------------------------------------------------------------------
// Kernel C: per batch  W1 = DW^T @ KV,  W2 = DW^T @ KW  (contraction over i),
// DW = exp(-alpha*11*dis) computed ON THE FLY during the A-tile smem fill
// (no 128 MB DW scratch, no separate dw kernel). Both GEMMs share the A tile;
// fused epilogue emits out = sigmoid(Q) * W1 / W2.
// Tile: 128(J) x 64(D) x 16(I). 256 threads, (8x4)x2 microtile per thread.
// ---------------------------------------------------------------------------
__global__ __launch_bounds__(256) void main_kernel(
    float* __restrict__ out,
    const float* __restrict__ dis,
    const float* __restrict__ alpha)
{
    __shared__ float As [16][132];   // exp-weighted dis tile [i][j], pad 4
    __shared__ float Bkv[16][68];    // KV tile [i][d]
    __shared__ float Bkw[16][68];    // KW tile [i][d]

    const int b  = blockIdx.z;
    const int j0 = blockIdx.y * 128;
    const int d0 = blockIdx.x * 64;
    const int tid = threadIdx.x;
    const int tx = tid & 15;         // 0..15 -> 4 d-cols each
    const int ty = tid >> 4;         // 0..15 -> 8 j-rows each

    const float coef = -alpha[0] * 11.0f;   // log2(2048) = 11 exactly

    const float* __restrict__ Db  = dis  + (size_t)b * NN * NN;
    const float* __restrict__ KVb = g_KV + (size_t)b * NN * DD;
    const float* __restrict__ KWb = g_KW + (size_t)b * NN * DD;

    const int a_j = (tid & 31) * 4;  // float4 col in A tile
    const int a_i = tid >> 5;        // 0..7 (two passes: +0, +8)
    const int b_d = (tid & 15) * 4;  // float4 col in B tiles
    const int b_i = tid >> 4;        // 0..15

    float acc1[8][4] = {}, acc2[8][4] = {};

    for (int i0 = 0; i0 < NN; i0 += 16) {
        float4 a0 = *(const float4*)&Db[(size_t)(i0 + a_i    ) * NN + j0 + a_j];
        float4 a1 = *(const float4*)&Db[(size_t)(i0 + a_i + 8) * NN + j0 + a_j];
        float4 v0 = *(const float4*)&KVb[(size_t)(i0 + b_i) * DD + d0 + b_d];
        float4 w0 = *(const float4*)&KWb[(size_t)(i0 + b_i) * DD + d0 + b_d];
        a0.x = expf(coef * a0.x); a0.y = expf(coef * a0.y);
        a0.z = expf(coef * a0.z); a0.w = expf(coef * a0.w);
        a1.x = expf(coef * a1.x); a1.y = expf(coef * a1.y);
        a1.z = expf(coef * a1.z); a1.w = expf(coef * a1.w);
        *(float4*)&As [a_i    ][a_j] = a0;
        *(float4*)&As [a_i + 8][a_j] = a1;
        *(float4*)&Bkv[b_i][b_d] = v0;
        *(float4*)&Bkw[b_i][b_d] = w0;
        __syncthreads();

        #pragma unroll
        for (int kk = 0; kk < 16; kk++) {
            float4 aj0 = *(const float4*)&As[kk][ty * 8];
            float4 aj1 = *(const float4*)&As[kk][ty * 8 + 4];
            float4 bv  = *(const float4*)&Bkv[kk][tx * 4];
            float4 bw  = *(const float4*)&Bkw[kk][tx * 4];
            float aj[8] = {aj0.x, aj0.y, aj0.z, aj0.w, aj1.x, aj1.y, aj1.z, aj1.w};
            float bva[4] = {bv.x, bv.y, bv.z, bv.w};
            float bwa[4] = {bw.x, bw.y, bw.z, bw.w};
            #pragma unroll
            for (int r = 0; r < 8; r++) {
                #pragma unroll
                for (int c = 0; c < 4; c++) {
                    acc1[r][c] += aj[r] * bva[c];
                    acc2[r][c] += aj[r] * bwa[c];
                }
            }
        }
        __syncthreads();
    }

    const float* __restrict__ Qb = g_Q + (size_t)b * NN * DD;
    float* __restrict__ outb = out + (size_t)b * NN * DD;
    #pragma unroll
    for (int r = 0; r < 8; r++) {
        const int j = j0 + ty * 8 + r;
        const size_t base = (size_t)j * DD + d0 + tx * 4;
        float4 q4 = *(const float4*)&Qb[base];
        float o0 = (1.0f / (1.0f + expf(-q4.x))) * acc1[r][0] / acc2[r][0];
        float o1 = (1.0f / (1.0f + expf(-q4.y))) * acc1[r][1] / acc2[r][1];
        float o2 = (1.0f / (1.0f + expf(-q4.z))) * acc1[r][2] / acc2[r][2];
        float o3 = (1.0f / (1.0f + expf(-q4.w))) * acc1[r][3] / acc2[r][3];
        *(float4*)&outb[base] = make_float4(o0, o1, o2, o3);
    }
}

// ---------------------------------------------------------------------------
extern "C" void kernel_launch(void* const* d_in, const int* in_sizes, int n_in,
                              void* d_out, int out_size)
{
    const float* x     = (const float*)d_in[0];
    const float* dis   = (const float*)d_in[1];
    const float* Wq    = (const float*)d_in[2];
    const float* Wk    = (const float*)d_in[3];
    const float* Wv    = (const float*)d_in[4];
    const float* alpha = (const float*)d_in[5];
    float* out = (float*)d_out;

    dim3 gA(DD / 64, (BB * NN) / 64);          // (8, 256)
    qkv_kernel<<<gA, 256>>>(x, Wq, Wk, Wv);

    dim3 gC(DD / 64, NN / 128, BB);            // (8, 16, 8)
    main_kernel<<<gC, 256>>>(out, dis, alpha);
}

// round 8
// speedup vs baseline: 2.1241x; 2.1241x over previous
#include <cuda_runtime.h>
#include <cuda_fp16.h>
#include <math.h>
#include <stdint.h>

#define BB 8
#define NN 2048
#define DD 512

// ---------------------------------------------------------------------------
// Scratch (__device__ globals). 64 MB total.
// ---------------------------------------------------------------------------
__device__ float g_Q [(size_t)BB * NN * DD];                        // 32 MB
__device__ __align__(16) __half g_KVT[(size_t)BB * DD * NN];        // 16 MB [b][d][i]
__device__ __align__(16) __half g_KWT[(size_t)BB * DD * NN];        // 16 MB [b][d][i]

// ---------------------------------------------------------------------------
// helpers
// ---------------------------------------------------------------------------
__device__ __forceinline__ uint32_t smem_u32(const void* p) {
    uint32_t a;
    asm("{ .reg .u64 t; cvta.to.shared.u64 t, %1; cvt.u32.u64 %0, t; }" : "=r"(a) : "l"(p));
    return a;
}

__device__ __forceinline__ void ldsm_x4_t(uint32_t* r, uint32_t addr) {
    asm volatile("ldmatrix.sync.aligned.m8n8.x4.trans.shared.b16 {%0,%1,%2,%3}, [%4];"
        : "=r"(r[0]), "=r"(r[1]), "=r"(r[2]), "=r"(r[3]) : "r"(addr));
}
__device__ __forceinline__ void ldsm_x4(uint32_t* r, uint32_t addr) {
    asm volatile("ldmatrix.sync.aligned.m8n8.x4.shared.b16 {%0,%1,%2,%3}, [%4];"
        : "=r"(r[0]), "=r"(r[1]), "=r"(r[2]), "=r"(r[3]) : "r"(addr));
}
__device__ __forceinline__ void mma16816(float* c, const uint32_t* a, uint32_t b0, uint32_t b1) {
    asm volatile("mma.sync.aligned.m16n8k16.row.col.f32.f16.f16.f32 "
        "{%0,%1,%2,%3}, {%4,%5,%6,%7}, {%8,%9}, {%0,%1,%2,%3};"
        : "+f"(c[0]), "+f"(c[1]), "+f"(c[2]), "+f"(c[3])
        : "r"(a[0]), "r"(a[1]), "r"(a[2]), "r"(a[3]), "r"(b0), "r"(b1));
}

// ---------------------------------------------------------------------------
// Kernel A: fused QKV projection (SIMT fp32). Epilogue writes:
//   g_Q fp32 [b*NN+i][d];  g_KVT/g_KWT fp16 TRANSPOSED [b][d][i].
// ---------------------------------------------------------------------------
__global__ __launch_bounds__(256) void qkv_kernel(
    const float* __restrict__ x,
    const float* __restrict__ Wq,
    const float* __restrict__ Wk,
    const float* __restrict__ Wv)
{
    __shared__ float Xs[16][68];
    __shared__ float Qs[16][68];
    __shared__ float Ks[16][68];
    __shared__ float Vs[16][68];
    __shared__ float Ts[64][65];     // transpose staging [n_local][d_local]

    const int tid = threadIdx.x;
    const int tx  = tid & 15;
    const int ty  = tid >> 4;
    const int row0 = blockIdx.y * 64;
    const int col0 = blockIdx.x * 64;
    const int lr = tid >> 2;
    const int lc = (tid & 3) * 4;

    float accq[4][4] = {}, acck[4][4] = {}, accv[4][4] = {};

    for (int c0 = 0; c0 < DD; c0 += 16) {
        float4 xv = *(const float4*)&x [(size_t)(row0 + lr) * DD + c0 + lc];
        float4 wq = *(const float4*)&Wq[(size_t)(col0 + lr) * DD + c0 + lc];
        float4 wk = *(const float4*)&Wk[(size_t)(col0 + lr) * DD + c0 + lc];
        float4 wv = *(const float4*)&Wv[(size_t)(col0 + lr) * DD + c0 + lc];
        Xs[lc + 0][lr] = xv.x; Xs[lc + 1][lr] = xv.y; Xs[lc + 2][lr] = xv.z; Xs[lc + 3][lr] = xv.w;
        Qs[lc + 0][lr] = wq.x; Qs[lc + 1][lr] = wq.y; Qs[lc + 2][lr] = wq.z; Qs[lc + 3][lr] = wq.w;
        Ks[lc + 0][lr] = wk.x; Ks[lc + 1][lr] = wk.y; Ks[lc + 2][lr] = wk.z; Ks[lc + 3][lr] = wk.w;
        Vs[lc + 0][lr] = wv.x; Vs[lc + 1][lr] = wv.y; Vs[lc + 2][lr] = wv.z; Vs[lc + 3][lr] = wv.w;
        __syncthreads();

        #pragma unroll
        for (int kk = 0; kk < 16; kk++) {
            float4 xr = *(const float4*)&Xs[kk][ty * 4];
            float4 qc = *(const float4*)&Qs[kk][tx * 4];
            float4 kc = *(const float4*)&Ks[kk][tx * 4];
            float4 vc = *(const float4*)&Vs[kk][tx * 4];
            float xa[4] = {xr.x, xr.y, xr.z, xr.w};
            float qa[4] = {qc.x, qc.y, qc.z, qc.w};
            float ka[4] = {kc.x, kc.y, kc.z, kc.w};
            float va[4] = {vc.x, vc.y, vc.z, vc.w};
            #pragma unroll
            for (int r = 0; r < 4; r++)
                #pragma unroll
                for (int c = 0; c < 4; c++) {
                    accq[r][c] += xa[r] * qa[c];
                    acck[r][c] += xa[r] * ka[c];
                    accv[r][c] += xa[r] * va[c];
                }
        }
        __syncthreads();
    }

    // Q (fp32, untransposed)
    #pragma unroll
    for (int r = 0; r < 4; r++) {
        const int n = row0 + ty * 4 + r;
        *(float4*)&g_Q[(size_t)n * DD + col0 + tx * 4] =
            make_float4(accq[r][0], accq[r][1], accq[r][2], accq[r][3]);
    }

    // Transposed fp16 writes for KV (pass 0) and KW (pass 1)
    const int b     = row0 >> 11;        // /NN
    const int i0loc = row0 & (NN - 1);
    const int wty = tid >> 4;            // d group
    const int wtx = tid & 15;            // i group

    #pragma unroll
    for (int pass = 0; pass < 2; pass++) {
        __syncthreads();
        #pragma unroll
        for (int r = 0; r < 4; r++)
            #pragma unroll
            for (int c = 0; c < 4; c++) {
                float ew = expf(acck[r][c]);
                Ts[ty * 4 + r][tx * 4 + c] = pass ? ew : ew * accv[r][c];
            }
        __syncthreads();

        __half* dst = pass ? g_KWT : g_KVT;
        #pragma unroll
        for (int r = 0; r < 4; r++) {
            const int d = col0 + wty * 4 + r;
            __half2 p0 = __floats2half2_rn(Ts[wtx * 4 + 0][wty * 4 + r],
                                           Ts[wtx * 4 + 1][wty * 4 + r]);
            __half2 p1 = __floats2half2_rn(Ts[wtx * 4 + 2][wty * 4 + r],
                                           Ts[wtx * 4 + 3][wty * 4 + r]);
            const size_t addr = ((size_t)b * DD + d) * NN + i0loc + wtx * 4;
            __half2* o = (__half2*)&dst[addr];
            o[0] = p0;
            o[1] = p1;
        }
    }
}

// ---------------------------------------------------------------------------
// Kernel C: mma.sync fp16 GEMM pair with on-the-fly DW = exp(coef*dis).
// CTA: 128 j x 64 d; 8 warps as 4(j) x 2(d), warp tile 32x32.
// K = 2048 in chunks of 64. A stored smem [k][j] fp16 (ldmatrix.x4.trans),
// B tiles [d][i] fp16 (ldmatrix.x4). Register-staged double buffer.
// Epilogue: out = sigmoid(Q) * W1 / W2.
// ---------------------------------------------------------------------------
#define KC     64
#define A_ST   136                       // halves per A row (128 + 8 pad)
#define B_ST   72                        // halves per B row (64 + 8 pad)
#define STAGE_H (KC * A_ST + 2 * (64 * B_ST))   // 17920 halves
#define SMEM_BYTES (2 * STAGE_H * 2)            // 71680 B

__global__ __launch_bounds__(256) void main_mma_kernel(
    float* __restrict__ out,
    const float* __restrict__ dis,
    const float* __restrict__ alpha)
{
    extern __shared__ __half sh[];
    const uint32_t sbase = smem_u32(sh);
    const int tid = threadIdx.x;
    const int w   = tid >> 5;
    const int l   = tid & 31;

    const int b  = blockIdx.z;
    const int j0 = blockIdx.y * 128;
    const int d0 = blockIdx.x * 64;
    const int jw = (w >> 1) * 32;        // warp j offset in CTA
    const int dw = (w & 1) * 32;         // warp d offset in CTA

    const float coef = -alpha[0] * 11.0f;     // log2(2048) = 11

    const float* __restrict__ disb = dis   + (size_t)b * NN * NN + j0;
    const __half* __restrict__ kvb = g_KVT + ((size_t)b * DD + d0) * NN;
    const __half* __restrict__ kwb = g_KWT + ((size_t)b * DD + d0) * NN;

    // ldmatrix lane addressing
    const int a_kl = ((l >> 4) << 3) + (l & 7);            // k row within 16-step
    const int a_jc = jw + (((l >> 3) & 1) << 3);           // j col (+ mt*16 later)
    const int b_nr = dw + (((l >> 4) & 1) << 3) + (l & 7); // d row (+ np*16 later)
    const int b_kc = ((l >> 3) & 1) << 3;                  // k col (+ ks*16 later)

    float acc1[2][4][4] = {};
    float acc2[2][4][4] = {};
    float4 av[8];
    uint4  bv[2], bw[2];

    // ---- load chunk `ch` into registers ----
    #define LOAD_CH(ch) do {                                                       \
        _Pragma("unroll")                                                          \
        for (int p = 0; p < 8; p++) {                                              \
            int idx = tid + (p << 8); int row = idx >> 5; int c4 = (idx & 31) << 2;\
            av[p] = *(const float4*)&disb[(size_t)((ch) * 64 + row) * NN + c4];    \
        }                                                                          \
        _Pragma("unroll")                                                          \
        for (int p = 0; p < 2; p++) {                                              \
            int idx = tid + (p << 8); int row = idx >> 3; int sg = idx & 7;        \
            bv[p] = *(const uint4*)&kvb[(size_t)row * NN + (ch) * 64 + sg * 8];    \
            bw[p] = *(const uint4*)&kwb[(size_t)row * NN + (ch) * 64 + sg * 8];    \
        }                                                                          \
    } while (0)

    // ---- exp/convert registers -> stage s ----
    #define STORE_CH(s) do {                                                       \
        __half* A  = sh + (s) * STAGE_H;                                           \
        __half* BV = A + KC * A_ST;                                                \
        __half* BW = BV + 64 * B_ST;                                               \
        _Pragma("unroll")                                                          \
        for (int p = 0; p < 8; p++) {                                              \
            int idx = tid + (p << 8); int row = idx >> 5; int c4 = (idx & 31) << 2;\
            float4 v = av[p];                                                      \
            __half2 h0 = __floats2half2_rn(__expf(coef * v.x), __expf(coef * v.y));\
            __half2 h1 = __floats2half2_rn(__expf(coef * v.z), __expf(coef * v.w));\
            __half2* dsta = (__half2*)&A[row * A_ST + c4];                         \
            dsta[0] = h0; dsta[1] = h1;                                            \
        }                                                                          \
        _Pragma("unroll")                                                          \
        for (int p = 0; p < 2; p++) {                                              \
            int idx = tid + (p << 8); int row = idx >> 3; int sg = idx & 7;        \
            *(uint4*)&BV[row * B_ST + sg * 8] = bv[p];                             \
            *(uint4*)&BW[row * B_ST + sg * 8] = bw[p];                             \
        }                                                                          \
    } while (0)

    LOAD_CH(0);
    STORE_CH(0);

    int s = 0;
    for (int ch = 0; ch < NN / KC; ch++) {
        __syncthreads();
        if (ch + 1 < NN / KC) LOAD_CH(ch + 1);

        // ---- MMA on stage s ----
        const uint32_t Ab  = sbase + s * STAGE_H * 2;
        const uint32_t BVb = Ab  + KC * A_ST * 2;
        const uint32_t BWb = BVb + 64 * B_ST * 2;
        #pragma unroll
        for (int ks = 0; ks < 4; ks++) {
            uint32_t a[2][4];
            #pragma unroll
            for (int mt = 0; mt < 2; mt++)
                ldsm_x4_t(a[mt], Ab + (uint32_t)(((ks * 16 + a_kl) * A_ST + a_jc + mt * 16) * 2));
            uint32_t fv[2][4], fw[2][4];
            #pragma unroll
            for (int np = 0; np < 2; np++) {
                const uint32_t boff = (uint32_t)(((b_nr + np * 16) * B_ST + ks * 16 + b_kc) * 2);
                ldsm_x4(fv[np], BVb + boff);
                ldsm_x4(fw[np], BWb + boff);
            }
            #pragma unroll
            for (int mt = 0; mt < 2; mt++)
                #pragma unroll
                for (int nt = 0; nt < 4; nt++) {
                    const int np = nt >> 1, o = (nt & 1) * 2;
                    mma16816(acc1[mt][nt], a[mt], fv[np][o], fv[np][o + 1]);
                    mma16816(acc2[mt][nt], a[mt], fw[np][o], fw[np][o + 1]);
                }
        }

        if (ch + 1 < NN / KC) STORE_CH(s ^ 1);
        s ^= 1;
    }

    // ---- epilogue: out = sigmoid(q) * W1 / W2 ----
    const int g = l >> 2, t = l & 3;
    #pragma unroll
    for (int mt = 0; mt < 2; mt++)
        #pragma unroll
        for (int nt = 0; nt < 4; nt++) {
            const int j  = j0 + jw + mt * 16 + g;
            const int d  = d0 + dw + nt * 8 + t * 2;
            const size_t b0a = ((size_t)b * NN + j) * DD + d;
            const size_t b1a = b0a + (size_t)8 * DD;
            float2 q0 = *(const float2*)&g_Q[b0a];
            float2 q1 = *(const float2*)&g_Q[b1a];
            float2 o0, o1;
            o0.x = (1.0f / (1.0f + __expf(-q0.x))) * acc1[mt][nt][0] / acc2[mt][nt][0];
            o0.y = (1.0f / (1.0f + __expf(-q0.y))) * acc1[mt][nt][1] / acc2[mt][nt][1];
            o1.x = (1.0f / (1.0f + __expf(-q1.x))) * acc1[mt][nt][2] / acc2[mt][nt][2];
            o1.y = (1.0f / (1.0f + __expf(-q1.y))) * acc1[mt][nt][3] / acc2[mt][nt][3];
            *(float2*)&out[b0a] = o0;
            *(float2*)&out[b1a] = o1;
        }
}

// ---------------------------------------------------------------------------
extern "C" void kernel_launch(void* const* d_in, const int* in_sizes, int n_in,
                              void* d_out, int out_size)
{
    const float* x     = (const float*)d_in[0];
    const float* dis   = (const float*)d_in[1];
    const float* Wq    = (const float*)d_in[2];
    const float* Wk    = (const float*)d_in[3];
    const float* Wv    = (const float*)d_in[4];
    const float* alpha = (const float*)d_in[5];
    float* out = (float*)d_out;

    static int smem_set = 0;
    if (!smem_set) {
        cudaFuncSetAttribute(main_mma_kernel,
                             cudaFuncAttributeMaxDynamicSharedMemorySize, SMEM_BYTES);
        smem_set = 1;
    }

    dim3 gA(DD / 64, (BB * NN) / 64);          // (8, 256)
    qkv_kernel<<<gA, 256>>>(x, Wq, Wk, Wv);

    dim3 gC(DD / 64, NN / 128, BB);            // (8, 16, 8)
    main_mma_kernel<<<gC, 256, SMEM_BYTES>>>(out, dis, alpha);
}